// round 7
// baseline (speedup 1.0000x reference)
#include <cuda_runtime.h>

// Problem constants
#define E_      4
#define B_      16384
#define STATE_  29
#define ACT_    8
#define HID_    512

// Tiling
#define TR        32          // batch rows per CTA
#define KT        16          // k-tile staged in SMEM for the 512x512 layer
#define NTHREADS  256
#define HROW      520         // padded SMEM row stride (floats) - kills bank conflicts

typedef unsigned long long u64;

// Scratch (device globals: no allocation allowed in kernel_launch)
__device__ float g_legs_diff[(size_t)E_ * 4 * B_ * 4];        // (E, 4, B, 4)  = 4 MB
__device__ float g_state_out[(size_t)E_ * B_ * STATE_];       // (E, B, 29)    = 7.6 MB

// ---------------- packed fp32x2 helpers (Blackwell) ----------------
__device__ __forceinline__ u64 fma2(u64 a, u64 b, u64 c) {
    u64 d;
    asm("fma.rn.f32x2 %0, %1, %2, %3;" : "=l"(d) : "l"(a), "l"(b), "l"(c));
    return d;
}
__device__ __forceinline__ u64 pack2(float x, float y) {
    u64 r;
    asm("mov.b64 %0, {%1, %2};" : "=l"(r)
        : "r"(__float_as_uint(x)), "r"(__float_as_uint(y)));
    return r;
}
__device__ __forceinline__ void unpack2(u64 v, float& x, float& y) {
    unsigned lo, hi;
    asm("mov.b64 {%0, %1}, %2;" : "=r"(lo), "=r"(hi) : "l"(v));
    x = __uint_as_float(lo);
    y = __uint_as_float(hi);
}

// ---------------- layer 0: IN -> 512, relu, result into Hs ----------------
// Thread (warp wrp, lane) owns rows wrp*4..+3 and float-pairs at cols 2*(lane+32*u).
template <int IN>
__device__ __forceinline__ void dense_in_relu(float* Hs, const float* Xs,
                                              const float* __restrict__ W0,
                                              const float* __restrict__ B0, int t) {
    const int lane = t & 31, wrp = t >> 5;
    const u64* W0v = (const u64*)W0;   // row i starts at i*256 (u64 units)
    const u64* B0v = (const u64*)B0;
#pragma unroll
    for (int r = 0; r < 4; r++) {
        const int row = wrp * 4 + r;
        float xv[IN];
#pragma unroll
        for (int i = 0; i < IN; i++) xv[i] = Xs[row * 32 + i];
#pragma unroll
        for (int u = 0; u < 8; u++) {
            const int cu = lane + 32 * u;            // u64 column index
            u64 a = B0v[cu];                         // start from bias
#pragma unroll
            for (int i = 0; i < IN; i++) {
                u64 w = W0v[(size_t)i * (HID_ / 2) + cu];
                a = fma2(pack2(xv[i], xv[i]), w, a);
            }
            float x, y;
            unpack2(a, x, y);
            *(u64*)&Hs[row * HROW + 2 * cu] = pack2(fmaxf(x, 0.f), fmaxf(y, 0.f));
        }
    }
}

// ---------------- layer 1: 512 -> 512, relu, in-place on Hs ----------------
__device__ __forceinline__ void dense512_relu(float* Hs, float* Ws,
                                              const float* __restrict__ W1,
                                              const float* __restrict__ B1, int t) {
    const int lane = t & 31, wrp = t >> 5;
    u64 acc[4][8];
#pragma unroll
    for (int r = 0; r < 4; r++)
#pragma unroll
        for (int u = 0; u < 8; u++) acc[r][u] = 0ull;

    for (int kt = 0; kt < HID_; kt += KT) {
        __syncthreads();   // protect Ws reuse (also orders Hs writes on entry)
        // stage W1 rows [kt, kt+KT) into SMEM: 8192 floats, 8 float4 per thread
        const float4* src = (const float4*)(W1 + (size_t)kt * HID_);
        float4* dst = (float4*)Ws;
#pragma unroll
        for (int q = 0; q < (KT * HID_ / 4) / NTHREADS; q++)
            dst[q * NTHREADS + t] = src[q * NTHREADS + t];
        __syncthreads();

#pragma unroll
        for (int kk = 0; kk < KT; kk++) {
            const int k = kt + kk;
            float a0 = Hs[(wrp * 4 + 0) * HROW + k];
            float a1 = Hs[(wrp * 4 + 1) * HROW + k];
            float a2 = Hs[(wrp * 4 + 2) * HROW + k];
            float a3 = Hs[(wrp * 4 + 3) * HROW + k];
            u64 p0 = pack2(a0, a0), p1 = pack2(a1, a1);
            u64 p2 = pack2(a2, a2), p3 = pack2(a3, a3);
            const u64* w8 = (const u64*)(Ws + kk * HID_) + lane;  // stride-32 u64 -> conflict-free
#pragma unroll
            for (int u = 0; u < 8; u++) {
                u64 w = w8[u * 32];
                acc[0][u] = fma2(p0, w, acc[0][u]);
                acc[1][u] = fma2(p1, w, acc[1][u]);
                acc[2][u] = fma2(p2, w, acc[2][u]);
                acc[3][u] = fma2(p3, w, acc[3][u]);
            }
        }
    }
    __syncthreads();   // everyone done reading Hs
    // bias + relu + writeback
#pragma unroll
    for (int r = 0; r < 4; r++) {
        const int row = wrp * 4 + r;
#pragma unroll
        for (int u = 0; u < 8; u++) {
            const int c = 2 * lane + 64 * u;
            float x, y;
            unpack2(acc[r][u], x, y);
            x = fmaxf(x + B1[c], 0.f);
            y = fmaxf(y + B1[c + 1], 0.f);
            *(u64*)&Hs[row * HROW + c] = pack2(x, y);
        }
    }
    __syncthreads();
}

// =======================================================================
// Kernel 1: leg MLP over (E, 4B) rows -> g_legs_diff
// =======================================================================
__global__ void __launch_bounds__(NTHREADS, 2)
leg_kernel(const float* __restrict__ state, const float* __restrict__ act,
           const float* __restrict__ wl0, const float* __restrict__ bl0,
           const float* __restrict__ wl1, const float* __restrict__ bl1,
           const float* __restrict__ wl2, const float* __restrict__ bl2,
           const float* __restrict__ mu_leg, const float* __restrict__ sigma_leg,
           const float* __restrict__ mu_t_leg, const float* __restrict__ sigma_t_leg) {
    extern __shared__ float smem[];
    float* Hs = smem;                      // TR * HROW
    float* Ws = smem + TR * HROW;          // KT * HID
    float* Xs = Ws + KT * HID_;            // TR * 32

    const int e = blockIdx.y;
    const int row0 = blockIdx.x * TR;
    const int t = threadIdx.x;

    // build normalized leg inputs: row = j*B + b, feats per reference _leg_inputs
    for (int q = t; q < TR * 6; q += NTHREADS) {
        int r = q / 6, i = q % 6;
        int grow = row0 + r;
        int j = grow >> 14;           // / B_
        int b = grow & (B_ - 1);
        const float* st = state + ((size_t)e * B_ + b) * STATE_;
        const float* ac = act + ((size_t)e * B_ + b) * ACT_;
        float v;
        if (i == 0)      v = st[13 + 2 * j];
        else if (i == 1) v = st[21 + 2 * j];
        else if (i == 2) v = st[14 + 2 * j];
        else if (i == 3) v = st[22 + 2 * j];
        else if (i == 4) v = ac[2 * j];
        else             v = ac[2 * j + 1];
        Xs[r * 32 + i] = (v - mu_leg[i]) / (sigma_leg[i] + 1e-8f);
    }
    __syncthreads();

    dense_in_relu<6>(Hs, Xs, wl0 + (size_t)e * 6 * HID_, bl0 + (size_t)e * HID_, t);
    dense512_relu(Hs, Ws, wl1 + (size_t)e * HID_ * HID_, bl1 + (size_t)e * HID_, t);

    // layer 2: 512 -> 8 (only first 4 outputs kept). Stage wl2 in SMEM.
    const float* W2 = wl2 + (size_t)e * HID_ * 8;
    for (int q = t; q < HID_ * 8; q += NTHREADS) Ws[q] = W2[q];
    __syncthreads();

    const int row = t >> 3, col = t & 7;
    float s = 0.f;
#pragma unroll 8
    for (int k = 0; k < HID_; k++)
        s += Hs[row * HROW + k] * Ws[k * 8 + col];
    s += bl2[e * 8 + col];
    if (col < 4) {
        float d = s * (sigma_t_leg[col] + 1e-8f) + mu_t_leg[col];
        g_legs_diff[((size_t)e * 4 * B_ + row0 + row) * 4 + col] = d;
    }
}

// =======================================================================
// Kernel 2: pose MLP over (E, B) rows -> g_state_out (full 29-dim next state)
// =======================================================================
__global__ void __launch_bounds__(NTHREADS, 2)
pose_kernel(const float* __restrict__ state,
            const float* __restrict__ wp0, const float* __restrict__ bp0,
            const float* __restrict__ wp1, const float* __restrict__ bp1,
            const float* __restrict__ wp2, const float* __restrict__ bp2,
            const float* __restrict__ mu_pose, const float* __restrict__ sigma_pose,
            const float* __restrict__ mu_t_pose, const float* __restrict__ sigma_t_pose) {
    extern __shared__ float smem[];
    float* Hs = smem;
    float* Ws = smem + TR * HROW;
    float* Xs = Ws + KT * HID_;

    const int e = blockIdx.y;
    const int b0 = blockIdx.x * TR;
    const int t = threadIdx.x;

    // pose_in = [state[:13], legs_diff_fmt(16)], normalized
    for (int q = t; q < TR * STATE_; q += NTHREADS) {
        int r = q / STATE_, c = q % STATE_;
        int b = b0 + r;
        float v;
        if (c < 13) {
            v = state[((size_t)e * B_ + b) * STATE_ + c];
        } else {
            int m = c - 13;
            int j, comp;
            if (m < 8) { j = m >> 1; comp = (m & 1) ? 2 : 0; }
            else       { int m2 = m - 8; j = m2 >> 1; comp = (m2 & 1) ? 3 : 1; }
            v = g_legs_diff[((size_t)e * 4 * B_ + (size_t)j * B_ + b) * 4 + comp];
        }
        Xs[r * 32 + c] = (v - mu_pose[c]) / (sigma_pose[c] + 1e-8f);
    }
    __syncthreads();

    dense_in_relu<29>(Hs, Xs, wp0 + (size_t)e * STATE_ * HID_, bp0 + (size_t)e * HID_, t);
    dense512_relu(Hs, Ws, wp1 + (size_t)e * HID_ * HID_, bp1 + (size_t)e * HID_, t);

    // layer 2: 512 -> 26, only cols 0..12 needed. Stage packed [512 x 13].
    const float* W2 = wp2 + (size_t)e * HID_ * 26;
    for (int q = t; q < HID_ * 13; q += NTHREADS) {
        int k = q / 13, c = q % 13;
        Ws[q] = W2[k * 26 + c];
    }
    __syncthreads();

    const int row = t >> 3, col = t & 7;
    const int b = b0 + row;
    const bool two = (col < 5);
    float s0 = 0.f, s1 = 0.f;
#pragma unroll 4
    for (int k = 0; k < HID_; k++) {
        float h = Hs[row * HROW + k];
        s0 += h * Ws[k * 13 + col];
        if (two) s1 += h * Ws[k * 13 + col + 8];
    }
    {
        const float* st = state + ((size_t)e * B_ + b) * STATE_;
        float* o = g_state_out + ((size_t)e * B_ + b) * STATE_;
        float v0 = s0 + bp2[e * 26 + col];
        o[col] = v0 * (sigma_t_pose[col] + 1e-8f) + mu_t_pose[col] + st[col];
        if (two) {
            int c2 = col + 8;
            float v1 = s1 + bp2[e * 26 + c2];
            o[c2] = v1 * (sigma_t_pose[c2] + 1e-8f) + mu_t_pose[c2] + st[c2];
        }
    }

    // leg part of next_state: interleaved curr + diff (cols 13..28)
    if (t < TR) {
        int bb = b0 + t;
        const float* st = state + ((size_t)e * B_ + bb) * STATE_;
        float* o = g_state_out + ((size_t)e * B_ + bb) * STATE_;
#pragma unroll
        for (int j = 0; j < 4; j++) {
            const float* d = g_legs_diff + ((size_t)e * 4 * B_ + (size_t)j * B_ + bb) * 4;
            o[13 + 2 * j] = st[13 + 2 * j] + d[0];
            o[14 + 2 * j] = st[14 + 2 * j] + d[2];
            o[21 + 2 * j] = st[21 + 2 * j] + d[1];
            o[22 + 2 * j] = st[22 + 2 * j] + d[3];
        }
    }
}

// =======================================================================
// Kernel 3: ensemble mean
// =======================================================================
__global__ void mean_kernel(float* __restrict__ out) {
    const size_t n4 = (size_t)B_ * STATE_ / 4;     // 118784 float4s
    const float4* s0 = (const float4*)g_state_out;
    const float4* s1 = (const float4*)(g_state_out + (size_t)1 * B_ * STATE_);
    const float4* s2 = (const float4*)(g_state_out + (size_t)2 * B_ * STATE_);
    const float4* s3 = (const float4*)(g_state_out + (size_t)3 * B_ * STATE_);
    for (size_t i = blockIdx.x * blockDim.x + threadIdx.x; i < n4;
         i += (size_t)gridDim.x * blockDim.x) {
        float4 a = s0[i], b = s1[i], c = s2[i], d = s3[i];
        float4 r;
        r.x = 0.25f * (a.x + b.x + c.x + d.x);
        r.y = 0.25f * (a.y + b.y + c.y + d.y);
        r.z = 0.25f * (a.z + b.z + c.z + d.z);
        r.w = 0.25f * (a.w + b.w + c.w + d.w);
        ((float4*)out)[i] = r;
    }
}

extern "C" void kernel_launch(void* const* d_in, const int* in_sizes, int n_in,
                              void* d_out, int out_size) {
    const float* state      = (const float*)d_in[0];
    const float* act        = (const float*)d_in[1];
    const float* wl0        = (const float*)d_in[2];
    const float* bl0        = (const float*)d_in[3];
    const float* wl1        = (const float*)d_in[4];
    const float* bl1        = (const float*)d_in[5];
    const float* wl2        = (const float*)d_in[6];
    const float* bl2        = (const float*)d_in[7];
    const float* wp0        = (const float*)d_in[8];
    const float* bp0        = (const float*)d_in[9];
    const float* wp1        = (const float*)d_in[10];
    const float* bp1        = (const float*)d_in[11];
    const float* wp2        = (const float*)d_in[12];
    const float* bp2        = (const float*)d_in[13];
    const float* mu_leg     = (const float*)d_in[14];
    const float* sigma_leg  = (const float*)d_in[15];
    const float* mu_pose    = (const float*)d_in[16];
    const float* sigma_pose = (const float*)d_in[17];
    const float* mu_t_leg   = (const float*)d_in[18];
    const float* sigma_t_leg= (const float*)d_in[19];
    const float* mu_t_pose  = (const float*)d_in[20];
    const float* sigma_t_pose=(const float*)d_in[21];

    const int smem = (TR * HROW + KT * HID_ + TR * 32) * (int)sizeof(float);  // ~101 KB
    cudaFuncSetAttribute(leg_kernel, cudaFuncAttributeMaxDynamicSharedMemorySize, smem);
    cudaFuncSetAttribute(pose_kernel, cudaFuncAttributeMaxDynamicSharedMemorySize, smem);

    dim3 g1(4 * B_ / TR, E_);   // 2048 x 4 CTAs
    leg_kernel<<<g1, NTHREADS, smem>>>(state, act, wl0, bl0, wl1, bl1, wl2, bl2,
                                       mu_leg, sigma_leg, mu_t_leg, sigma_t_leg);

    dim3 g2(B_ / TR, E_);       // 512 x 4 CTAs
    pose_kernel<<<g2, NTHREADS, smem>>>(state, wp0, bp0, wp1, bp1, wp2, bp2,
                                        mu_pose, sigma_pose, mu_t_pose, sigma_t_pose);

    mean_kernel<<<256, 256>>>((float*)d_out);
}

// round 8
// speedup vs baseline: 1.0028x; 1.0028x over previous
#include <cuda_runtime.h>

// Problem constants
#define E_      4
#define B_      16384
#define STATE_  29
#define ACT_    8
#define HID_    512

// Tiling
#define TR        32          // batch rows per CTA
#define KT        16          // k-tile staged in SMEM for the 512x512 layer
#define NTHREADS  256
#define HROW      520         // padded SMEM row stride (floats) - kills bank conflicts

typedef unsigned long long u64;

// Scratch (device globals: no allocation allowed in kernel_launch)
__device__ float g_legs_diff[(size_t)E_ * 4 * B_ * 4];        // (E, 4, B, 4)  = 4 MB
__device__ float g_state_out[(size_t)E_ * B_ * STATE_];       // (E, B, 29)    = 7.6 MB

// ---------------- packed fp32x2 helpers (Blackwell) ----------------
__device__ __forceinline__ u64 fma2(u64 a, u64 b, u64 c) {
    u64 d;
    asm("fma.rn.f32x2 %0, %1, %2, %3;" : "=l"(d) : "l"(a), "l"(b), "l"(c));
    return d;
}
__device__ __forceinline__ u64 pack2(float x, float y) {
    u64 r;
    asm("mov.b64 %0, {%1, %2};" : "=l"(r)
        : "r"(__float_as_uint(x)), "r"(__float_as_uint(y)));
    return r;
}
__device__ __forceinline__ void unpack2(u64 v, float& x, float& y) {
    unsigned lo, hi;
    asm("mov.b64 {%0, %1}, %2;" : "=r"(lo), "=r"(hi) : "l"(v));
    x = __uint_as_float(lo);
    y = __uint_as_float(hi);
}

// ---------------- layer 0: IN -> 512, relu, result into Hs ----------------
// Thread (warp wrp, lane) owns rows wrp*4..+3 and float-pairs at cols 2*(lane+32*u).
template <int IN>
__device__ __forceinline__ void dense_in_relu(float* Hs, const float* Xs,
                                              const float* __restrict__ W0,
                                              const float* __restrict__ B0, int t) {
    const int lane = t & 31, wrp = t >> 5;
    const u64* W0v = (const u64*)W0;   // row i starts at i*256 (u64 units)
    const u64* B0v = (const u64*)B0;
#pragma unroll
    for (int r = 0; r < 4; r++) {
        const int row = wrp * 4 + r;
        float xv[IN];
#pragma unroll
        for (int i = 0; i < IN; i++) xv[i] = Xs[row * 32 + i];
#pragma unroll
        for (int u = 0; u < 8; u++) {
            const int cu = lane + 32 * u;            // u64 column index
            u64 a = B0v[cu];                         // start from bias
#pragma unroll
            for (int i = 0; i < IN; i++) {
                u64 w = W0v[(size_t)i * (HID_ / 2) + cu];
                a = fma2(pack2(xv[i], xv[i]), w, a);
            }
            float x, y;
            unpack2(a, x, y);
            *(u64*)&Hs[row * HROW + 2 * cu] = pack2(fmaxf(x, 0.f), fmaxf(y, 0.f));
        }
    }
}

// ---------------- layer 1: 512 -> 512, relu, in-place on Hs ----------------
__device__ __forceinline__ void dense512_relu(float* Hs, float* Ws,
                                              const float* __restrict__ W1,
                                              const float* __restrict__ B1, int t) {
    const int lane = t & 31, wrp = t >> 5;
    u64 acc[4][8];
#pragma unroll
    for (int r = 0; r < 4; r++)
#pragma unroll
        for (int u = 0; u < 8; u++) acc[r][u] = 0ull;

    for (int kt = 0; kt < HID_; kt += KT) {
        __syncthreads();   // protect Ws reuse (also orders Hs writes on entry)
        // stage W1 rows [kt, kt+KT) into SMEM: 8192 floats, 8 float4 per thread
        const float4* src = (const float4*)(W1 + (size_t)kt * HID_);
        float4* dst = (float4*)Ws;
#pragma unroll
        for (int q = 0; q < (KT * HID_ / 4) / NTHREADS; q++)
            dst[q * NTHREADS + t] = src[q * NTHREADS + t];
        __syncthreads();

#pragma unroll
        for (int kk = 0; kk < KT; kk++) {
            const int k = kt + kk;
            float a0 = Hs[(wrp * 4 + 0) * HROW + k];
            float a1 = Hs[(wrp * 4 + 1) * HROW + k];
            float a2 = Hs[(wrp * 4 + 2) * HROW + k];
            float a3 = Hs[(wrp * 4 + 3) * HROW + k];
            u64 p0 = pack2(a0, a0), p1 = pack2(a1, a1);
            u64 p2 = pack2(a2, a2), p3 = pack2(a3, a3);
            const u64* w8 = (const u64*)(Ws + kk * HID_) + lane;  // stride-32 u64 -> conflict-free
#pragma unroll
            for (int u = 0; u < 8; u++) {
                u64 w = w8[u * 32];
                acc[0][u] = fma2(p0, w, acc[0][u]);
                acc[1][u] = fma2(p1, w, acc[1][u]);
                acc[2][u] = fma2(p2, w, acc[2][u]);
                acc[3][u] = fma2(p3, w, acc[3][u]);
            }
        }
    }
    __syncthreads();   // everyone done reading Hs
    // bias + relu + writeback
#pragma unroll
    for (int r = 0; r < 4; r++) {
        const int row = wrp * 4 + r;
#pragma unroll
        for (int u = 0; u < 8; u++) {
            const int c = 2 * lane + 64 * u;
            float x, y;
            unpack2(acc[r][u], x, y);
            x = fmaxf(x + B1[c], 0.f);
            y = fmaxf(y + B1[c + 1], 0.f);
            *(u64*)&Hs[row * HROW + c] = pack2(x, y);
        }
    }
    __syncthreads();
}

// =======================================================================
// Kernel 1: leg MLP over (E, 4B) rows -> g_legs_diff
// =======================================================================
__global__ void __launch_bounds__(NTHREADS, 2)
leg_kernel(const float* __restrict__ state, const float* __restrict__ act,
           const float* __restrict__ wl0, const float* __restrict__ bl0,
           const float* __restrict__ wl1, const float* __restrict__ bl1,
           const float* __restrict__ wl2, const float* __restrict__ bl2,
           const float* __restrict__ mu_leg, const float* __restrict__ sigma_leg,
           const float* __restrict__ mu_t_leg, const float* __restrict__ sigma_t_leg) {
    extern __shared__ float smem[];
    float* Hs = smem;                      // TR * HROW
    float* Ws = smem + TR * HROW;          // KT * HID
    float* Xs = Ws + KT * HID_;            // TR * 32

    const int e = blockIdx.y;
    const int row0 = blockIdx.x * TR;
    const int t = threadIdx.x;

    // build normalized leg inputs: row = j*B + b, feats per reference _leg_inputs
    for (int q = t; q < TR * 6; q += NTHREADS) {
        int r = q / 6, i = q % 6;
        int grow = row0 + r;
        int j = grow >> 14;           // / B_
        int b = grow & (B_ - 1);
        const float* st = state + ((size_t)e * B_ + b) * STATE_;
        const float* ac = act + ((size_t)e * B_ + b) * ACT_;
        float v;
        if (i == 0)      v = st[13 + 2 * j];
        else if (i == 1) v = st[21 + 2 * j];
        else if (i == 2) v = st[14 + 2 * j];
        else if (i == 3) v = st[22 + 2 * j];
        else if (i == 4) v = ac[2 * j];
        else             v = ac[2 * j + 1];
        Xs[r * 32 + i] = (v - mu_leg[i]) / (sigma_leg[i] + 1e-8f);
    }
    __syncthreads();

    dense_in_relu<6>(Hs, Xs, wl0 + (size_t)e * 6 * HID_, bl0 + (size_t)e * HID_, t);
    dense512_relu(Hs, Ws, wl1 + (size_t)e * HID_ * HID_, bl1 + (size_t)e * HID_, t);

    // layer 2: 512 -> 8 (only first 4 outputs kept). Stage wl2 in SMEM.
    const float* W2 = wl2 + (size_t)e * HID_ * 8;
    for (int q = t; q < HID_ * 8; q += NTHREADS) Ws[q] = W2[q];
    __syncthreads();

    const int row = t >> 3, col = t & 7;
    float s = 0.f;
#pragma unroll 8
    for (int k = 0; k < HID_; k++)
        s += Hs[row * HROW + k] * Ws[k * 8 + col];
    s += bl2[e * 8 + col];
    if (col < 4) {
        float d = s * (sigma_t_leg[col] + 1e-8f) + mu_t_leg[col];
        g_legs_diff[((size_t)e * 4 * B_ + row0 + row) * 4 + col] = d;
    }
}

// =======================================================================
// Kernel 2: pose MLP over (E, B) rows -> g_state_out (full 29-dim next state)
// =======================================================================
__global__ void __launch_bounds__(NTHREADS, 2)
pose_kernel(const float* __restrict__ state,
            const float* __restrict__ wp0, const float* __restrict__ bp0,
            const float* __restrict__ wp1, const float* __restrict__ bp1,
            const float* __restrict__ wp2, const float* __restrict__ bp2,
            const float* __restrict__ mu_pose, const float* __restrict__ sigma_pose,
            const float* __restrict__ mu_t_pose, const float* __restrict__ sigma_t_pose) {
    extern __shared__ float smem[];
    float* Hs = smem;
    float* Ws = smem + TR * HROW;
    float* Xs = Ws + KT * HID_;

    const int e = blockIdx.y;
    const int b0 = blockIdx.x * TR;
    const int t = threadIdx.x;

    // pose_in = [state[:13], legs_diff_fmt(16)], normalized
    for (int q = t; q < TR * STATE_; q += NTHREADS) {
        int r = q / STATE_, c = q % STATE_;
        int b = b0 + r;
        float v;
        if (c < 13) {
            v = state[((size_t)e * B_ + b) * STATE_ + c];
        } else {
            int m = c - 13;
            int j, comp;
            if (m < 8) { j = m >> 1; comp = (m & 1) ? 2 : 0; }
            else       { int m2 = m - 8; j = m2 >> 1; comp = (m2 & 1) ? 3 : 1; }
            v = g_legs_diff[((size_t)e * 4 * B_ + (size_t)j * B_ + b) * 4 + comp];
        }
        Xs[r * 32 + c] = (v - mu_pose[c]) / (sigma_pose[c] + 1e-8f);
    }
    __syncthreads();

    dense_in_relu<29>(Hs, Xs, wp0 + (size_t)e * STATE_ * HID_, bp0 + (size_t)e * HID_, t);
    dense512_relu(Hs, Ws, wp1 + (size_t)e * HID_ * HID_, bp1 + (size_t)e * HID_, t);

    // layer 2: 512 -> 26, only cols 0..12 needed. Stage packed [512 x 13].
    const float* W2 = wp2 + (size_t)e * HID_ * 26;
    for (int q = t; q < HID_ * 13; q += NTHREADS) {
        int k = q / 13, c = q % 13;
        Ws[q] = W2[k * 26 + c];
    }
    __syncthreads();

    const int row = t >> 3, col = t & 7;
    const int b = b0 + row;
    const bool two = (col < 5);
    float s0 = 0.f, s1 = 0.f;
#pragma unroll 4
    for (int k = 0; k < HID_; k++) {
        float h = Hs[row * HROW + k];
        s0 += h * Ws[k * 13 + col];
        if (two) s1 += h * Ws[k * 13 + col + 8];
    }
    {
        const float* st = state + ((size_t)e * B_ + b) * STATE_;
        float* o = g_state_out + ((size_t)e * B_ + b) * STATE_;
        float v0 = s0 + bp2[e * 26 + col];
        o[col] = v0 * (sigma_t_pose[col] + 1e-8f) + mu_t_pose[col] + st[col];
        if (two) {
            int c2 = col + 8;
            float v1 = s1 + bp2[e * 26 + c2];
            o[c2] = v1 * (sigma_t_pose[c2] + 1e-8f) + mu_t_pose[c2] + st[c2];
        }
    }

    // leg part of next_state: interleaved curr + diff (cols 13..28)
    if (t < TR) {
        int bb = b0 + t;
        const float* st = state + ((size_t)e * B_ + bb) * STATE_;
        float* o = g_state_out + ((size_t)e * B_ + bb) * STATE_;
#pragma unroll
        for (int j = 0; j < 4; j++) {
            const float* d = g_legs_diff + ((size_t)e * 4 * B_ + (size_t)j * B_ + bb) * 4;
            o[13 + 2 * j] = st[13 + 2 * j] + d[0];
            o[14 + 2 * j] = st[14 + 2 * j] + d[2];
            o[21 + 2 * j] = st[21 + 2 * j] + d[1];
            o[22 + 2 * j] = st[22 + 2 * j] + d[3];
        }
    }
}

// =======================================================================
// Kernel 3: ensemble mean
// =======================================================================
__global__ void mean_kernel(float* __restrict__ out) {
    const size_t n4 = (size_t)B_ * STATE_ / 4;     // 118784 float4s
    const float4* s0 = (const float4*)g_state_out;
    const float4* s1 = (const float4*)(g_state_out + (size_t)1 * B_ * STATE_);
    const float4* s2 = (const float4*)(g_state_out + (size_t)2 * B_ * STATE_);
    const float4* s3 = (const float4*)(g_state_out + (size_t)3 * B_ * STATE_);
    for (size_t i = blockIdx.x * blockDim.x + threadIdx.x; i < n4;
         i += (size_t)gridDim.x * blockDim.x) {
        float4 a = s0[i], b = s1[i], c = s2[i], d = s3[i];
        float4 r;
        r.x = 0.25f * (a.x + b.x + c.x + d.x);
        r.y = 0.25f * (a.y + b.y + c.y + d.y);
        r.z = 0.25f * (a.z + b.z + c.z + d.z);
        r.w = 0.25f * (a.w + b.w + c.w + d.w);
        ((float4*)out)[i] = r;
    }
}

extern "C" void kernel_launch(void* const* d_in, const int* in_sizes, int n_in,
                              void* d_out, int out_size) {
    const float* state      = (const float*)d_in[0];
    const float* act        = (const float*)d_in[1];
    const float* wl0        = (const float*)d_in[2];
    const float* bl0        = (const float*)d_in[3];
    const float* wl1        = (const float*)d_in[4];
    const float* bl1        = (const float*)d_in[5];
    const float* wl2        = (const float*)d_in[6];
    const float* bl2        = (const float*)d_in[7];
    const float* wp0        = (const float*)d_in[8];
    const float* bp0        = (const float*)d_in[9];
    const float* wp1        = (const float*)d_in[10];
    const float* bp1        = (const float*)d_in[11];
    const float* wp2        = (const float*)d_in[12];
    const float* bp2        = (const float*)d_in[13];
    const float* mu_leg     = (const float*)d_in[14];
    const float* sigma_leg  = (const float*)d_in[15];
    const float* mu_pose    = (const float*)d_in[16];
    const float* sigma_pose = (const float*)d_in[17];
    const float* mu_t_leg   = (const float*)d_in[18];
    const float* sigma_t_leg= (const float*)d_in[19];
    const float* mu_t_pose  = (const float*)d_in[20];
    const float* sigma_t_pose=(const float*)d_in[21];

    const int smem = (TR * HROW + KT * HID_ + TR * 32) * (int)sizeof(float);  // ~101 KB
    cudaFuncSetAttribute(leg_kernel, cudaFuncAttributeMaxDynamicSharedMemorySize, smem);
    cudaFuncSetAttribute(pose_kernel, cudaFuncAttributeMaxDynamicSharedMemorySize, smem);

    dim3 g1(4 * B_ / TR, E_);   // 2048 x 4 CTAs
    leg_kernel<<<g1, NTHREADS, smem>>>(state, act, wl0, bl0, wl1, bl1, wl2, bl2,
                                       mu_leg, sigma_leg, mu_t_leg, sigma_t_leg);

    dim3 g2(B_ / TR, E_);       // 512 x 4 CTAs
    pose_kernel<<<g2, NTHREADS, smem>>>(state, wp0, bp0, wp1, bp1, wp2, bp2,
                                        mu_pose, sigma_pose, mu_t_pose, sigma_t_pose);

    mean_kernel<<<256, 256>>>((float*)d_out);
}